// round 14
// baseline (speedup 1.0000x reference)
#include <cuda_runtime.h>
#include <cuda_bf16.h>
#include <cstdint>
#include <cstring>

typedef unsigned int u32;

#define D        512
#define KT       32                  // D/16 k-tiles
#define BDIM     1024
#define C        200
#define NKEYS    50000
#define BM       128
#define BN       128
#define NTILES   391
#define NPAD     (NTILES * BN)       // 50048
#define NT16     (NPAD / 16)         // 3128
#define BTILES   (BDIM / BM)         // 8
#define NGROUPS  18                  // 8*18 = 144 CTAs = one wave
#define NTHREADS 512
#define CP       201                 // csh row stride (floats, odd)
#define SMEM_DYN (BM * CP * 4)       // 102912

// ---------------- device scratch (fragment-major layouts) ----------------
__device__ __align__(16) uint4 g_qfrag[BDIM / 16][KT][32];
__device__ __align__(16) uint4 g_kfrag[NT16][KT][32];    // tail tiles stay zero
__device__ float g_qf[BDIM * D];
__device__ float g_tf[C * D];
__device__ int   g_lab[NPAD];
__device__ float g_part[NGROUPS * BDIM * C];

// ---------------- helpers ----------------
__device__ __forceinline__ u32 bf2u(__nv_bfloat162 v) {
    u32 r;
    memcpy(&r, &v, 4);
    return r;
}

__device__ __forceinline__ void mma_bf16(float* d, const u32* a, const u32* b) {
    asm volatile(
        "mma.sync.aligned.m16n8k16.row.col.f32.bf16.bf16.f32 "
        "{%0,%1,%2,%3}, {%4,%5,%6,%7}, {%8,%9}, {%0,%1,%2,%3};\n"
        : "+f"(d[0]), "+f"(d[1]), "+f"(d[2]), "+f"(d[3])
        : "r"(a[0]), "r"(a[1]), "r"(a[2]), "r"(a[3]), "r"(b[0]), "r"(b[1]));
}

__device__ __forceinline__ uint4 ldg_keep(const uint4* p) {
    uint4 v;
    asm volatile("ld.global.nc.L1::evict_last.v4.u32 {%0,%1,%2,%3}, [%4];"
                 : "=r"(v.x), "=r"(v.y), "=r"(v.z), "=r"(v.w) : "l"(p));
    return v;
}
__device__ __forceinline__ uint4 ldg_stream(const uint4* p) {
    uint4 v;
    asm volatile("ld.global.nc.L1::evict_first.v4.u32 {%0,%1,%2,%3}, [%4];"
                 : "=r"(v.x), "=r"(v.y), "=r"(v.z), "=r"(v.w) : "l"(p));
    return v;
}

// ---------------- prep: normalize + write fragment-major tiles ----------------
__global__ void __launch_bounds__(512) prep_q(const float* __restrict__ img) {
    __shared__ u32 sh[16][260];
    int t = threadIdx.x, w = t >> 5, l = t & 31;
    int row = blockIdx.x * 16 + w;
    const float4* src = (const float4*)(img + row * D);
    float4 v[4]; float ss = 0.f;
#pragma unroll
    for (int j = 0; j < 4; j++) {
        v[j] = src[j * 32 + l];
        ss += v[j].x * v[j].x + v[j].y * v[j].y + v[j].z * v[j].z + v[j].w * v[j].w;
    }
#pragma unroll
    for (int o = 16; o; o >>= 1) ss += __shfl_xor_sync(0xffffffffu, ss, o);
    float inv = rsqrtf(ss);
    float4* qf = (float4*)(g_qf + row * D);
#pragma unroll
    for (int j = 0; j < 4; j++) {
        float4 y = make_float4(v[j].x * inv, v[j].y * inv, v[j].z * inv, v[j].w * inv);
        qf[j * 32 + l] = y;
        int col = (j * 32 + l) * 2;
        sh[w][col]     = bf2u(__floats2bfloat162_rn(y.x, y.y));
        sh[w][col + 1] = bf2u(__floats2bfloat162_rn(y.z, y.w));
    }
    __syncthreads();
#pragma unroll
    for (int s = t; s < 1024; s += 512) {
        int kt = s >> 5, ln = s & 31;
        int ka = kt * 8 + (ln & 3), kb = ka + 4, r0 = ln >> 2;
        uint4 f;
        f.x = sh[r0][ka]; f.y = sh[r0 + 8][ka]; f.z = sh[r0][kb]; f.w = sh[r0 + 8][kb];
        g_qfrag[blockIdx.x][kt][ln] = f;
    }
}

__global__ void __launch_bounds__(512) prep_k(const float* __restrict__ keys,
                                              const int* __restrict__ labels) {
    __shared__ u32 sh[16][260];
    int t = threadIdx.x, w = t >> 5, l = t & 31;
    int row = blockIdx.x * 16 + w;
    const float4* src = (const float4*)(keys + row * D);
    float4 v[4]; float ss = 0.f;
#pragma unroll
    for (int j = 0; j < 4; j++) {
        v[j] = src[j * 32 + l];
        ss += v[j].x * v[j].x + v[j].y * v[j].y + v[j].z * v[j].z + v[j].w * v[j].w;
    }
#pragma unroll
    for (int o = 16; o; o >>= 1) ss += __shfl_xor_sync(0xffffffffu, ss, o);
    float inv = rsqrtf(ss);
#pragma unroll
    for (int j = 0; j < 4; j++) {
        int col = (j * 32 + l) * 2;
        sh[w][col]     = bf2u(__floats2bfloat162_rn(v[j].x * inv, v[j].y * inv));
        sh[w][col + 1] = bf2u(__floats2bfloat162_rn(v[j].z * inv, v[j].w * inv));
    }
    if (w == 0 && l < 16) {
        int rr = blockIdx.x * 16 + l;
        int lb = labels[rr];
        g_lab[rr] = (lb < 0) ? 0 : ((lb >= C) ? C - 1 : lb);
    }
    __syncthreads();
#pragma unroll
    for (int s = t; s < 1024; s += 512) {
        int kt = s >> 5, ln = s & 31;
        int ka = kt * 8 + (ln & 3), kb = ka + 4, n0 = ln >> 2;
        uint4 f;
        f.x = sh[n0][ka]; f.y = sh[n0][kb]; f.z = sh[n0 + 8][ka]; f.w = sh[n0 + 8][kb];
        g_kfrag[blockIdx.x][kt][ln] = f;
    }
}

// ---------------- main: barrier-free fragment GEMM, 2 n-tiles per pass ----------------
extern __shared__ float csh[];

__global__ void __launch_bounds__(NTHREADS, 1) gemm_scatter() {
    int tid = threadIdx.x;
    int lane = tid & 31, wid = tid >> 5;
    int wm = wid >> 2, wn = wid & 3;
    int bt = blockIdx.x;                      // 0..7
    int ng = blockIdx.y;                      // 0..17

    for (int i = tid; i < BM * CP; i += NTHREADS) csh[i] = 0.f;
    __syncthreads();

    int mt0 = bt * 8 + wm * 2;
    const uint4* A0 = &g_qfrag[mt0][0][lane];
    const uint4* A1 = &g_qfrag[mt0 + 1][0][lane];

    int nt = (NTILES - 1 - ng) / NGROUPS + 1;     // strided tiles: ng, ng+18, ...
    int tl = 0;

    // -------- pair path: 2 tiles per pass, warp tile 32x64 --------
    for (; tl + 1 < nt; tl += 2) {
        int ta = ng + tl * NGROUPS;
        int myt = (wn < 2) ? ta : (ta + NGROUPS);
        int n0w = myt * BN + (wn & 1) * 64;       // warp's 64-col base
        const uint4* Bw = &g_kfrag[myt * 8 + (wn & 1) * 4][0][lane];

        float acc[2][8][4];
#pragma unroll
        for (int mi = 0; mi < 2; mi++)
#pragma unroll
            for (int ni = 0; ni < 8; ni++)
#pragma unroll
                for (int e = 0; e < 4; e++) acc[mi][ni][e] = 0.f;

#pragma unroll 4
        for (int kt = 0; kt < KT; kt++) {
            uint4 av0 = ldg_keep(A0 + kt * 32);
            uint4 av1 = ldg_keep(A1 + kt * 32);
            uint4 bv0 = ldg_stream(Bw + kt * 32);
            uint4 bv1 = ldg_stream(Bw + (KT + kt) * 32);
            uint4 bv2 = ldg_stream(Bw + (2 * KT + kt) * 32);
            uint4 bv3 = ldg_stream(Bw + (3 * KT + kt) * 32);
            u32 Ar0[4] = {av0.x, av0.y, av0.z, av0.w};
            u32 Ar1[4] = {av1.x, av1.y, av1.z, av1.w};
            u32 Bp[8][2] = {{bv0.x, bv0.y}, {bv0.z, bv0.w},
                            {bv1.x, bv1.y}, {bv1.z, bv1.w},
                            {bv2.x, bv2.y}, {bv2.z, bv2.w},
                            {bv3.x, bv3.y}, {bv3.z, bv3.w}};
#pragma unroll
            for (int ni = 0; ni < 8; ni++) {
                mma_bf16(acc[0][ni], Ar0, Bp[ni]);
                mma_bf16(acc[1][ni], Ar1, Bp[ni]);
            }
        }

        if (n0w + 64 <= NKEYS) {                  // full warp span
#pragma unroll
            for (int mi = 0; mi < 2; mi++) {
#pragma unroll
                for (int ni = 0; ni < 8; ni++) {
                    int rb = wm * 32 + mi * 16 + (lane >> 2);
                    int c0 = ni * 8 + 2 * (lane & 3);
#pragma unroll
                    for (int e = 0; e < 4; e++) {
                        int r = rb + ((e >= 2) ? 8 : 0);
                        int n = n0w + c0 + (e & 1);
                        float v = __expf(5.0f * acc[mi][ni][e]);
                        atomicAdd(&csh[r * CP + __ldg(&g_lab[n])], v);
                    }
                }
            }
        } else {                                  // tail (tile 390)
#pragma unroll
            for (int mi = 0; mi < 2; mi++) {
#pragma unroll
                for (int ni = 0; ni < 8; ni++) {
                    int rb = wm * 32 + mi * 16 + (lane >> 2);
                    int c0 = ni * 8 + 2 * (lane & 3);
#pragma unroll
                    for (int e = 0; e < 4; e++) {
                        int r = rb + ((e >= 2) ? 8 : 0);
                        int n = n0w + c0 + (e & 1);
                        if (n < NKEYS) {
                            float v = __expf(5.0f * acc[mi][ni][e]);
                            atomicAdd(&csh[r * CP + __ldg(&g_lab[n])], v);
                        }
                    }
                }
            }
        }
    }

    // -------- leftover single tile: warp tile 32x32 (R13 body) --------
    if (tl < nt) {
        int ntile = ng + tl * NGROUPS;
        int n0 = ntile * BN;
        const uint4* B0 = &g_kfrag[ntile * 8 + wn * 2][0][lane];
        const uint4* B1 = B0 + KT * 32;

        float acc[2][4][4];
#pragma unroll
        for (int mi = 0; mi < 2; mi++)
#pragma unroll
            for (int ni = 0; ni < 4; ni++)
#pragma unroll
                for (int e = 0; e < 4; e++) acc[mi][ni][e] = 0.f;

#pragma unroll 8
        for (int kt = 0; kt < KT; kt++) {
            uint4 av0 = ldg_keep(A0 + kt * 32);
            uint4 av1 = ldg_keep(A1 + kt * 32);
            uint4 bv0 = ldg_stream(B0 + kt * 32);
            uint4 bv1 = ldg_stream(B1 + kt * 32);
            u32 Ar0[4] = {av0.x, av0.y, av0.z, av0.w};
            u32 Ar1[4] = {av1.x, av1.y, av1.z, av1.w};
            u32 Bp[4][2] = {{bv0.x, bv0.y}, {bv0.z, bv0.w},
                            {bv1.x, bv1.y}, {bv1.z, bv1.w}};
#pragma unroll
            for (int ni = 0; ni < 4; ni++) {
                mma_bf16(acc[0][ni], Ar0, Bp[ni]);
                mma_bf16(acc[1][ni], Ar1, Bp[ni]);
            }
        }

#pragma unroll
        for (int mi = 0; mi < 2; mi++) {
#pragma unroll
            for (int ni = 0; ni < 4; ni++) {
                int rb = wm * 32 + mi * 16 + (lane >> 2);
                int cb = wn * 32 + ni * 8 + 2 * (lane & 3);
#pragma unroll
                for (int e = 0; e < 4; e++) {
                    int r = rb + ((e >= 2) ? 8 : 0);
                    int n = n0 + cb + (e & 1);
                    if (n < NKEYS) {
                        float v = __expf(5.0f * acc[mi][ni][e]);
                        atomicAdd(&csh[r * CP + __ldg(&g_lab[n])], v);
                    }
                }
            }
        }
    }

    __syncthreads();
    float* dst = g_part + ((size_t)ng * BDIM + bt * BM) * C;
    for (int i = tid; i < BM * C; i += NTHREADS) {
        int r = i / C, c = i % C;
        dst[i] = csh[r * CP + c];
    }
}

// ---------------- z branch + combine partials ----------------
__global__ void __launch_bounds__(256) zcombine(float* __restrict__ out) {
    __shared__ float a2[64][17];
    __shared__ float b2[64][17];
    int tid = threadIdx.x;
    int tx = tid & 15, ty = tid >> 4;
    int rb = blockIdx.x * 64, cb = blockIdx.y * 64;

    float acc[4][4];
#pragma unroll
    for (int i = 0; i < 4; i++)
#pragma unroll
        for (int j = 0; j < 4; j++) acc[i][j] = 0.f;

    for (int k0 = 0; k0 < D; k0 += 16) {
        __syncthreads();
#pragma unroll
        for (int j = 0; j < 4; j++) {
            int idx = tid + j * 256;
            int r = idx >> 4, c = idx & 15;
            a2[r][c] = g_qf[(rb + r) * D + k0 + c];
            int cls = cb + r;
            b2[r][c] = (cls < C) ? g_tf[cls * D + k0 + c] : 0.f;
        }
        __syncthreads();
#pragma unroll
        for (int k = 0; k < 16; k++) {
            float av[4], bv[4];
#pragma unroll
            for (int i = 0; i < 4; i++) { av[i] = a2[ty * 4 + i][k]; bv[i] = b2[tx * 4 + i][k]; }
#pragma unroll
            for (int i = 0; i < 4; i++)
#pragma unroll
                for (int j = 0; j < 4; j++) acc[i][j] += av[i] * bv[j];
        }
    }

#pragma unroll
    for (int i = 0; i < 4; i++)
#pragma unroll
        for (int j = 0; j < 4; j++) {
            int r = rb + ty * 4 + i, c = cb + tx * 4 + j;
            if (c < C) {
                float s = 0.f;
#pragma unroll
                for (int gg = 0; gg < NGROUPS; gg++)
                    s += g_part[((size_t)gg * BDIM + r) * C + c];
                out[r * C + c] = 50.f * acc[i][j] + 0.5f * s;
            }
        }
}

__global__ void prep_t(const float* __restrict__ txt) {
    int row = blockIdx.x, t = threadIdx.x;
    float4 x = ((const float4*)(txt + row * D))[t];
    float ss = x.x * x.x + x.y * x.y + x.z * x.z + x.w * x.w;
#pragma unroll
    for (int o = 16; o; o >>= 1) ss += __shfl_xor_sync(0xffffffffu, ss, o);
    __shared__ float ws[4];
    if ((t & 31) == 0) ws[t >> 5] = ss;
    __syncthreads();
    float inv = rsqrtf(ws[0] + ws[1] + ws[2] + ws[3]);
    ((float4*)(g_tf + row * D))[t] = make_float4(x.x * inv, x.y * inv, x.z * inv, x.w * inv);
}

// ---------------- launch ----------------
extern "C" void kernel_launch(void* const* d_in, const int* in_sizes, int n_in,
                              void* d_out, int out_size) {
    const float* img  = (const float*)d_in[0];
    const float* txt  = (const float*)d_in[1];
    const float* keys = (const float*)d_in[2];
    const int*   labs = (const int*)d_in[3];
    float* out = (float*)d_out;

    cudaFuncSetAttribute(gemm_scatter, cudaFuncAttributeMaxDynamicSharedMemorySize,
                         SMEM_DYN);

    prep_q<<<BDIM / 16, 512>>>(img);
    prep_t<<<C, 128>>>(txt);
    prep_k<<<NKEYS / 16, 512>>>(keys, labs);
    gemm_scatter<<<dim3(BTILES, NGROUPS), NTHREADS, SMEM_DYN>>>();
    zcombine<<<dim3(BDIM / 64, 4), 256>>>(out);
}

// round 15
// speedup vs baseline: 1.0745x; 1.0745x over previous
#include <cuda_runtime.h>
#include <cuda_bf16.h>
#include <cstdint>
#include <cstring>

typedef unsigned int u32;

#define D        512
#define KT       32                  // D/16 k-tiles
#define BDIM     1024
#define C        200
#define NKEYS    50000
#define BM       128
#define BN       128
#define NTILES   391
#define NPAD     (NTILES * BN)       // 50048
#define NT16     (NPAD / 16)         // 3128
#define BTILES   (BDIM / BM)         // 8
#define NGROUPS  18                  // 8*18 = 144 CTAs = one wave
#define NTHREADS 512
#define CP       201                 // csh row stride (floats, odd)
#define SMEM_DYN (BM * CP * 4)       // 102912

// ---------------- device scratch (fragment-major layouts) ----------------
__device__ __align__(16) uint4 g_qfrag[BDIM / 16][KT][32];
__device__ __align__(16) uint4 g_kfrag[NT16][KT][32];    // tail tiles stay zero
__device__ float g_qf[BDIM * D];
__device__ float g_tf[C * D];
__device__ int   g_lab[NPAD];
__device__ float g_part[NGROUPS * BDIM * C];

// ---------------- helpers ----------------
__device__ __forceinline__ u32 bf2u(__nv_bfloat162 v) {
    u32 r;
    memcpy(&r, &v, 4);
    return r;
}

// NOTE: non-volatile asm — lets ptxas software-pipeline loads across kt
// iterations (ordering is enforced purely by register dependencies).
__device__ __forceinline__ void mma_bf16(float* d, const u32* a, const u32* b) {
    asm("mma.sync.aligned.m16n8k16.row.col.f32.bf16.bf16.f32 "
        "{%0,%1,%2,%3}, {%4,%5,%6,%7}, {%8,%9}, {%0,%1,%2,%3};\n"
        : "+f"(d[0]), "+f"(d[1]), "+f"(d[2]), "+f"(d[3])
        : "r"(a[0]), "r"(a[1]), "r"(a[2]), "r"(a[3]), "r"(b[0]), "r"(b[1]));
}

__device__ __forceinline__ uint4 ldg_keep(const uint4* p) {
    uint4 v;
    asm("ld.global.nc.L1::evict_last.v4.u32 {%0,%1,%2,%3}, [%4];"
        : "=r"(v.x), "=r"(v.y), "=r"(v.z), "=r"(v.w) : "l"(p));
    return v;
}
__device__ __forceinline__ uint4 ldg_stream(const uint4* p) {
    uint4 v;
    asm("ld.global.nc.L1::evict_first.v4.u32 {%0,%1,%2,%3}, [%4];"
        : "=r"(v.x), "=r"(v.y), "=r"(v.z), "=r"(v.w) : "l"(p));
    return v;
}

// ---------------- prep: normalize + write fragment-major tiles ----------------
__global__ void __launch_bounds__(512) prep_q(const float* __restrict__ img) {
    __shared__ u32 sh[16][260];
    int t = threadIdx.x, w = t >> 5, l = t & 31;
    int row = blockIdx.x * 16 + w;
    const float4* src = (const float4*)(img + row * D);
    float4 v[4]; float ss = 0.f;
#pragma unroll
    for (int j = 0; j < 4; j++) {
        v[j] = src[j * 32 + l];
        ss += v[j].x * v[j].x + v[j].y * v[j].y + v[j].z * v[j].z + v[j].w * v[j].w;
    }
#pragma unroll
    for (int o = 16; o; o >>= 1) ss += __shfl_xor_sync(0xffffffffu, ss, o);
    float inv = rsqrtf(ss);
    float4* qf = (float4*)(g_qf + row * D);
#pragma unroll
    for (int j = 0; j < 4; j++) {
        float4 y = make_float4(v[j].x * inv, v[j].y * inv, v[j].z * inv, v[j].w * inv);
        qf[j * 32 + l] = y;
        int col = (j * 32 + l) * 2;
        sh[w][col]     = bf2u(__floats2bfloat162_rn(y.x, y.y));
        sh[w][col + 1] = bf2u(__floats2bfloat162_rn(y.z, y.w));
    }
    __syncthreads();
#pragma unroll
    for (int s = t; s < 1024; s += 512) {
        int kt = s >> 5, ln = s & 31;
        int ka = kt * 8 + (ln & 3), kb = ka + 4, r0 = ln >> 2;
        uint4 f;
        f.x = sh[r0][ka]; f.y = sh[r0 + 8][ka]; f.z = sh[r0][kb]; f.w = sh[r0 + 8][kb];
        g_qfrag[blockIdx.x][kt][ln] = f;
    }
}

__global__ void __launch_bounds__(512) prep_k(const float* __restrict__ keys,
                                              const int* __restrict__ labels) {
    __shared__ u32 sh[16][260];
    int t = threadIdx.x, w = t >> 5, l = t & 31;
    int row = blockIdx.x * 16 + w;
    const float4* src = (const float4*)(keys + row * D);
    float4 v[4]; float ss = 0.f;
#pragma unroll
    for (int j = 0; j < 4; j++) {
        v[j] = src[j * 32 + l];
        ss += v[j].x * v[j].x + v[j].y * v[j].y + v[j].z * v[j].z + v[j].w * v[j].w;
    }
#pragma unroll
    for (int o = 16; o; o >>= 1) ss += __shfl_xor_sync(0xffffffffu, ss, o);
    float inv = rsqrtf(ss);
#pragma unroll
    for (int j = 0; j < 4; j++) {
        int col = (j * 32 + l) * 2;
        sh[w][col]     = bf2u(__floats2bfloat162_rn(v[j].x * inv, v[j].y * inv));
        sh[w][col + 1] = bf2u(__floats2bfloat162_rn(v[j].z * inv, v[j].w * inv));
    }
    if (w == 0 && l < 16) {
        int rr = blockIdx.x * 16 + l;
        int lb = labels[rr];
        g_lab[rr] = (lb < 0) ? 0 : ((lb >= C) ? C - 1 : lb);
    }
    __syncthreads();
#pragma unroll
    for (int s = t; s < 1024; s += 512) {
        int kt = s >> 5, ln = s & 31;
        int ka = kt * 8 + (ln & 3), kb = ka + 4, n0 = ln >> 2;
        uint4 f;
        f.x = sh[n0][ka]; f.y = sh[n0][kb]; f.z = sh[n0 + 8][ka]; f.w = sh[n0 + 8][kb];
        g_kfrag[blockIdx.x][kt][ln] = f;
    }
}

// ---------------- main: barrier-free direct-LDG fragment GEMM + scatter ----------------
extern __shared__ float csh[];

__global__ void __launch_bounds__(NTHREADS, 1) gemm_scatter() {
    int tid = threadIdx.x;
    int lane = tid & 31, wid = tid >> 5;
    int wm = wid >> 2, wn = wid & 3;          // 4x4 warps, warp tile 32x32
    int bt = blockIdx.x;                      // 0..7
    int ng = blockIdx.y;                      // 0..17

    for (int i = tid; i < BM * CP; i += NTHREADS) csh[i] = 0.f;
    __syncthreads();

    int mt0 = bt * 8 + wm * 2;
    const uint4* A0 = &g_qfrag[mt0][0][lane];
    const uint4* A1 = &g_qfrag[mt0 + 1][0][lane];

    int nt = (NTILES - 1 - ng) / NGROUPS + 1;     // strided tiles: ng, ng+18, ...
    for (int tl = 0; tl < nt; tl++) {
        int ntile = ng + tl * NGROUPS;
        int n0 = ntile * BN;
        const uint4* B0 = &g_kfrag[ntile * 8 + wn * 2][0][lane];
        const uint4* B1 = B0 + KT * 32;

        float acc[2][4][4];
#pragma unroll
        for (int mi = 0; mi < 2; mi++)
#pragma unroll
            for (int ni = 0; ni < 4; ni++)
#pragma unroll
                for (int e = 0; e < 4; e++) acc[mi][ni][e] = 0.f;

#pragma unroll 8
        for (int kt = 0; kt < KT; kt++) {
            uint4 av0 = ldg_keep(A0 + kt * 32);
            uint4 av1 = ldg_keep(A1 + kt * 32);
            uint4 bv0 = ldg_stream(B0 + kt * 32);
            uint4 bv1 = ldg_stream(B1 + kt * 32);
            u32 Ar0[4] = {av0.x, av0.y, av0.z, av0.w};
            u32 Ar1[4] = {av1.x, av1.y, av1.z, av1.w};
            u32 Bp[4][2] = {{bv0.x, bv0.y}, {bv0.z, bv0.w},
                            {bv1.x, bv1.y}, {bv1.z, bv1.w}};
#pragma unroll
            for (int ni = 0; ni < 4; ni++) {
                mma_bf16(acc[0][ni], Ar0, Bp[ni]);
                mma_bf16(acc[1][ni], Ar1, Bp[ni]);
            }
        }

        // epilogue: exp + label scatter into csh (atomics; no sync needed)
        if (n0 + BN <= NKEYS) {                   // full tile: no guards
#pragma unroll
            for (int mi = 0; mi < 2; mi++) {
#pragma unroll
                for (int ni = 0; ni < 4; ni++) {
                    int rb = wm * 32 + mi * 16 + (lane >> 2);
                    int cb = wn * 32 + ni * 8 + 2 * (lane & 3);
#pragma unroll
                    for (int e = 0; e < 4; e++) {
                        int r = rb + ((e >= 2) ? 8 : 0);
                        int c = cb + (e & 1);
                        float v = __expf(5.0f * acc[mi][ni][e]);
                        atomicAdd(&csh[r * CP + __ldg(&g_lab[n0 + c])], v);
                    }
                }
            }
        } else {                                  // tail tile (only ntile==390)
#pragma unroll
            for (int mi = 0; mi < 2; mi++) {
#pragma unroll
                for (int ni = 0; ni < 4; ni++) {
                    int rb = wm * 32 + mi * 16 + (lane >> 2);
                    int cb = wn * 32 + ni * 8 + 2 * (lane & 3);
#pragma unroll
                    for (int e = 0; e < 4; e++) {
                        int r = rb + ((e >= 2) ? 8 : 0);
                        int c = cb + (e & 1);
                        int n = n0 + c;
                        if (n < NKEYS) {
                            float v = __expf(5.0f * acc[mi][ni][e]);
                            atomicAdd(&csh[r * CP + __ldg(&g_lab[n])], v);
                        }
                    }
                }
            }
        }
    }

    __syncthreads();
    float* dst = g_part + ((size_t)ng * BDIM + bt * BM) * C;
    for (int i = tid; i < BM * C; i += NTHREADS) {
        int r = i / C, c = i % C;
        dst[i] = csh[r * CP + c];
    }
}

// ---------------- z branch + combine partials ----------------
__global__ void __launch_bounds__(256) zcombine(float* __restrict__ out) {
    __shared__ float a2[64][17];
    __shared__ float b2[64][17];
    int tid = threadIdx.x;
    int tx = tid & 15, ty = tid >> 4;
    int rb = blockIdx.x * 64, cb = blockIdx.y * 64;

    float acc[4][4];
#pragma unroll
    for (int i = 0; i < 4; i++)
#pragma unroll
        for (int j = 0; j < 4; j++) acc[i][j] = 0.f;

    for (int k0 = 0; k0 < D; k0 += 16) {
        __syncthreads();
#pragma unroll
        for (int j = 0; j < 4; j++) {
            int idx = tid + j * 256;
            int r = idx >> 4, c = idx & 15;
            a2[r][c] = g_qf[(rb + r) * D + k0 + c];
            int cls = cb + r;
            b2[r][c] = (cls < C) ? g_tf[cls * D + k0 + c] : 0.f;
        }
        __syncthreads();
#pragma unroll
        for (int k = 0; k < 16; k++) {
            float av[4], bv[4];
#pragma unroll
            for (int i = 0; i < 4; i++) { av[i] = a2[ty * 4 + i][k]; bv[i] = b2[tx * 4 + i][k]; }
#pragma unroll
            for (int i = 0; i < 4; i++)
#pragma unroll
                for (int j = 0; j < 4; j++) acc[i][j] += av[i] * bv[j];
        }
    }

#pragma unroll
    for (int i = 0; i < 4; i++)
#pragma unroll
        for (int j = 0; j < 4; j++) {
            int r = rb + ty * 4 + i, c = cb + tx * 4 + j;
            if (c < C) {
                float s = 0.f;
#pragma unroll
                for (int gg = 0; gg < NGROUPS; gg++)
                    s += g_part[((size_t)gg * BDIM + r) * C + c];
                out[r * C + c] = 50.f * acc[i][j] + 0.5f * s;
            }
        }
}

__global__ void prep_t(const float* __restrict__ txt) {
    int row = blockIdx.x, t = threadIdx.x;
    float4 x = ((const float4*)(txt + row * D))[t];
    float ss = x.x * x.x + x.y * x.y + x.z * x.z + x.w * x.w;
#pragma unroll
    for (int o = 16; o; o >>= 1) ss += __shfl_xor_sync(0xffffffffu, ss, o);
    __shared__ float ws[4];
    if ((t & 31) == 0) ws[t >> 5] = ss;
    __syncthreads();
    float inv = rsqrtf(ws[0] + ws[1] + ws[2] + ws[3]);
    ((float4*)(g_tf + row * D))[t] = make_float4(x.x * inv, x.y * inv, x.z * inv, x.w * inv);
}

// ---------------- launch ----------------
extern "C" void kernel_launch(void* const* d_in, const int* in_sizes, int n_in,
                              void* d_out, int out_size) {
    const float* img  = (const float*)d_in[0];
    const float* txt  = (const float*)d_in[1];
    const float* keys = (const float*)d_in[2];
    const int*   labs = (const int*)d_in[3];
    float* out = (float*)d_out;

    cudaFuncSetAttribute(gemm_scatter, cudaFuncAttributeMaxDynamicSharedMemorySize,
                         SMEM_DYN);

    prep_q<<<BDIM / 16, 512>>>(img);
    prep_t<<<C, 128>>>(txt);
    prep_k<<<NKEYS / 16, 512>>>(keys, labs);
    gemm_scatter<<<dim3(BTILES, NGROUPS), NTHREADS, SMEM_DYN>>>();
    zcombine<<<dim3(BDIM / 64, 4), 256>>>(out);
}

// round 16
// speedup vs baseline: 1.1187x; 1.0412x over previous
#include <cuda_runtime.h>
#include <cuda_bf16.h>
#include <cstdint>
#include <cstring>

typedef unsigned int u32;
#define FULLM 0xffffffffu

#define D        512
#define KT       32
#define BDIM     1024
#define C        200
#define NKEYS    50000
#define BM       128
#define BN       128
#define NTILES   391
#define NPAD     (NTILES * BN)       // 50048
#define NT16     (NPAD / 16)         // 3128
#define BTILES   (BDIM / BM)         // 8
#define NGROUPS  18                  // 144 CTAs = one wave
#define NTHREADS 512
#define CP       201
#define SMEM_DYN (BM * CP * 4)       // 102912

// ---------------- device scratch ----------------
__device__ __align__(16) uint4 g_qfrag[BDIM / 16][KT][32];
__device__ __align__(16) uint4 g_kfrag[NT16][KT][32];    // tail tiles stay zero
__device__ float g_qf[BDIM * D];
__device__ float g_tf[C * D];
__device__ int   g_lab[NPAD];        // label-sorted
__device__ int   g_perm[NPAD];       // sorted pos -> source row
__device__ int   g_hist[C];
__device__ int   g_cur[C];
__device__ float g_part[NGROUPS * BDIM * C];

// ---------------- helpers ----------------
__device__ __forceinline__ u32 bf2u(__nv_bfloat162 v) {
    u32 r;
    memcpy(&r, &v, 4);
    return r;
}

__device__ __forceinline__ void mma_bf16(float* d, const u32* a, const u32* b) {
    asm("mma.sync.aligned.m16n8k16.row.col.f32.bf16.bf16.f32 "
        "{%0,%1,%2,%3}, {%4,%5,%6,%7}, {%8,%9}, {%0,%1,%2,%3};\n"
        : "+f"(d[0]), "+f"(d[1]), "+f"(d[2]), "+f"(d[3])
        : "r"(a[0]), "r"(a[1]), "r"(a[2]), "r"(a[3]), "r"(b[0]), "r"(b[1]));
}

__device__ __forceinline__ uint4 ldg_keep(const uint4* p) {
    uint4 v;
    asm("ld.global.nc.L1::evict_last.v4.u32 {%0,%1,%2,%3}, [%4];"
        : "=r"(v.x), "=r"(v.y), "=r"(v.z), "=r"(v.w) : "l"(p));
    return v;
}
__device__ __forceinline__ uint4 ldg_stream(const uint4* p) {
    uint4 v;
    asm("ld.global.nc.L1::evict_first.v4.u32 {%0,%1,%2,%3}, [%4];"
        : "=r"(v.x), "=r"(v.y), "=r"(v.z), "=r"(v.w) : "l"(p));
    return v;
}

// ---------------- sort prep ----------------
__global__ void prep_zero() {
    int i = threadIdx.x;
    if (i < C) g_hist[i] = 0;
}
__global__ void prep_hist(const int* __restrict__ labels) {
    int i = blockIdx.x * blockDim.x + threadIdx.x;
    if (i < NKEYS) {
        int l = labels[i];
        l = (l < 0) ? 0 : ((l >= C) ? C - 1 : l);
        atomicAdd(&g_hist[l], 1);
    }
}
__global__ void prep_scan() {
    __shared__ int sh[C];
    int t = threadIdx.x;
    if (t < C) sh[t] = g_hist[t];
    __syncthreads();
    if (t == 0) {
        int acc = 0;
        for (int c = 0; c < C; c++) { int v = sh[c]; sh[c] = acc; acc += v; }
    }
    __syncthreads();
    if (t < C) g_cur[t] = sh[t];
}
__global__ void prep_perm(const int* __restrict__ labels) {
    int i = blockIdx.x * blockDim.x + threadIdx.x;
    if (i < NKEYS) {
        int l = labels[i];
        l = (l < 0) ? 0 : ((l >= C) ? C - 1 : l);
        int p = atomicAdd(&g_cur[l], 1);
        g_perm[p] = i;
        g_lab[p] = l;
    }
}

// ---------------- prep: normalize + fragment-major tiles ----------------
__global__ void __launch_bounds__(512) prep_q(const float* __restrict__ img) {
    __shared__ u32 sh[16][260];
    int t = threadIdx.x, w = t >> 5, l = t & 31;
    int row = blockIdx.x * 16 + w;
    const float4* src = (const float4*)(img + row * D);
    float4 v[4]; float ss = 0.f;
#pragma unroll
    for (int j = 0; j < 4; j++) {
        v[j] = src[j * 32 + l];
        ss += v[j].x * v[j].x + v[j].y * v[j].y + v[j].z * v[j].z + v[j].w * v[j].w;
    }
#pragma unroll
    for (int o = 16; o; o >>= 1) ss += __shfl_xor_sync(FULLM, ss, o);
    float inv = rsqrtf(ss);
    float4* qf = (float4*)(g_qf + row * D);
#pragma unroll
    for (int j = 0; j < 4; j++) {
        float4 y = make_float4(v[j].x * inv, v[j].y * inv, v[j].z * inv, v[j].w * inv);
        qf[j * 32 + l] = y;
        int col = (j * 32 + l) * 2;
        sh[w][col]     = bf2u(__floats2bfloat162_rn(y.x, y.y));
        sh[w][col + 1] = bf2u(__floats2bfloat162_rn(y.z, y.w));
    }
    __syncthreads();
#pragma unroll
    for (int s = t; s < 1024; s += 512) {
        int kt = s >> 5, ln = s & 31;
        int ka = kt * 8 + (ln & 3), kb = ka + 4, r0 = ln >> 2;
        uint4 f;
        f.x = sh[r0][ka]; f.y = sh[r0 + 8][ka]; f.z = sh[r0][kb]; f.w = sh[r0 + 8][kb];
        g_qfrag[blockIdx.x][kt][ln] = f;
    }
}

// gather sorted rows via perm; fragment build unchanged
__global__ void __launch_bounds__(512) prep_k(const float* __restrict__ keys) {
    __shared__ u32 sh[16][260];
    int t = threadIdx.x, w = t >> 5, l = t & 31;
    int srcrow = __ldg(&g_perm[blockIdx.x * 16 + w]);
    const float4* src = (const float4*)(keys + (size_t)srcrow * D);
    float4 v[4]; float ss = 0.f;
#pragma unroll
    for (int j = 0; j < 4; j++) {
        v[j] = src[j * 32 + l];
        ss += v[j].x * v[j].x + v[j].y * v[j].y + v[j].z * v[j].z + v[j].w * v[j].w;
    }
#pragma unroll
    for (int o = 16; o; o >>= 1) ss += __shfl_xor_sync(FULLM, ss, o);
    float inv = rsqrtf(ss);
#pragma unroll
    for (int j = 0; j < 4; j++) {
        int col = (j * 32 + l) * 2;
        sh[w][col]     = bf2u(__floats2bfloat162_rn(v[j].x * inv, v[j].y * inv));
        sh[w][col + 1] = bf2u(__floats2bfloat162_rn(v[j].z * inv, v[j].w * inv));
    }
    __syncthreads();
#pragma unroll
    for (int s = t; s < 1024; s += 512) {
        int kt = s >> 5, ln = s & 31;
        int ka = kt * 8 + (ln & 3), kb = ka + 4, n0 = ln >> 2;
        uint4 f;
        f.x = sh[n0][ka]; f.y = sh[n0][kb]; f.z = sh[n0 + 8][ka]; f.w = sh[n0 + 8][kb];
        g_kfrag[blockIdx.x][kt][ln] = f;
    }
}

// ---------------- main: fragment GEMM + sorted-label quad-merged scatter ----------------
extern __shared__ float csh[];

__global__ void __launch_bounds__(NTHREADS, 1) gemm_scatter() {
    int tid = threadIdx.x;
    int lane = tid & 31, wid = tid >> 5;
    int wm = wid >> 2, wn = wid & 3;          // 4x4 warps, warp tile 32x32
    int bt = blockIdx.x;
    int ng = blockIdx.y;

    for (int i = tid; i < BM * CP; i += NTHREADS) csh[i] = 0.f;
    __syncthreads();

    int mt0 = bt * 8 + wm * 2;
    const uint4* A0 = &g_qfrag[mt0][0][lane];
    const uint4* A1 = &g_qfrag[mt0 + 1][0][lane];

    const int coff[8] = {0, 1, 8, 9, 16, 17, 24, 25};   // ascending thread cols

    int nt = (NTILES - 1 - ng) / NGROUPS + 1;
    for (int tl = 0; tl < nt; tl++) {
        int ntile = ng + tl * NGROUPS;
        int n0 = ntile * BN;
        const uint4* B0 = &g_kfrag[ntile * 8 + wn * 2][0][lane];
        const uint4* B1 = B0 + KT * 32;

        float acc[2][4][4];
#pragma unroll
        for (int mi = 0; mi < 2; mi++)
#pragma unroll
            for (int ni = 0; ni < 4; ni++)
#pragma unroll
                for (int e = 0; e < 4; e++) acc[mi][ni][e] = 0.f;

#pragma unroll 8
        for (int kt = 0; kt < KT; kt++) {
            uint4 av0 = ldg_keep(A0 + kt * 32);
            uint4 av1 = ldg_keep(A1 + kt * 32);
            uint4 bv0 = ldg_stream(B0 + kt * 32);
            uint4 bv1 = ldg_stream(B1 + kt * 32);
            u32 Ar0[4] = {av0.x, av0.y, av0.z, av0.w};
            u32 Ar1[4] = {av1.x, av1.y, av1.z, av1.w};
            u32 Bp[4][2] = {{bv0.x, bv0.y}, {bv0.z, bv0.w},
                            {bv1.x, bv1.y}, {bv1.z, bv1.w}};
#pragma unroll
            for (int ni = 0; ni < 4; ni++) {
                mma_bf16(acc[0][ni], Ar0, Bp[ni]);
                mma_bf16(acc[1][ni], Ar1, Bp[ni]);
            }
        }

        if (n0 + BN <= NKEYS) {                   // full tile: sorted-label fast path
            int c0 = n0 + wn * 32 + 2 * (lane & 3);
            int l0  = __ldg(&g_lab[c0]);
            int l25 = __ldg(&g_lab[c0 + 25]);
            int pure = (l0 == l25) ? 1 : 0;
            // quad uniformity (lanes 0-3 of each quad share row set)
            int p = pure, lq = l0;
            int p1 = __shfl_xor_sync(FULLM, p, 1);
            int l1 = __shfl_xor_sync(FULLM, lq, 1);
            p = p & p1 & (lq == l1);
            int p2 = __shfl_xor_sync(FULLM, p, 2);
            int l2 = __shfl_xor_sync(FULLM, lq, 2);
            p = p & p2 & (lq == l2);

#pragma unroll
            for (int mi = 0; mi < 2; mi++) {
                int rA = wm * 32 + mi * 16 + (lane >> 2);
                float v0[8], v1[8];
#pragma unroll
                for (int ni = 0; ni < 4; ni++) {
                    v0[ni * 2]     = __expf(5.0f * acc[mi][ni][0]);
                    v0[ni * 2 + 1] = __expf(5.0f * acc[mi][ni][1]);
                    v1[ni * 2]     = __expf(5.0f * acc[mi][ni][2]);
                    v1[ni * 2 + 1] = __expf(5.0f * acc[mi][ni][3]);
                }
                float s0 = 0.f, s1 = 0.f;
#pragma unroll
                for (int k = 0; k < 8; k++) { s0 += v0[k]; s1 += v1[k]; }
                // quad reduce (pre-branch: all lanes converged)
                float t0 = s0 + __shfl_xor_sync(FULLM, s0, 1);
                t0 += __shfl_xor_sync(FULLM, t0, 2);
                float t1 = s1 + __shfl_xor_sync(FULLM, s1, 1);
                t1 += __shfl_xor_sync(FULLM, t1, 2);
                if (p) {
                    if ((lane & 3) == 0) {
                        atomicAdd(&csh[rA * CP + lq], t0);
                        atomicAdd(&csh[(rA + 8) * CP + lq], t1);
                    }
                } else if (pure) {
                    atomicAdd(&csh[rA * CP + l0], s0);
                    atomicAdd(&csh[(rA + 8) * CP + l0], s1);
                } else {
                    int cur = -1; float r0 = 0.f, r1 = 0.f;
#pragma unroll
                    for (int k = 0; k < 8; k++) {
                        int lk = __ldg(&g_lab[c0 + coff[k]]);
                        if (lk != cur) {
                            if (cur >= 0) {
                                atomicAdd(&csh[rA * CP + cur], r0);
                                atomicAdd(&csh[(rA + 8) * CP + cur], r1);
                            }
                            cur = lk; r0 = 0.f; r1 = 0.f;
                        }
                        r0 += v0[k]; r1 += v1[k];
                    }
                    atomicAdd(&csh[rA * CP + cur], r0);
                    atomicAdd(&csh[(rA + 8) * CP + cur], r1);
                }
            }
        } else {                                  // tail tile (ntile==390): guarded path
#pragma unroll
            for (int mi = 0; mi < 2; mi++) {
#pragma unroll
                for (int ni = 0; ni < 4; ni++) {
                    int rb = wm * 32 + mi * 16 + (lane >> 2);
                    int cb = wn * 32 + ni * 8 + 2 * (lane & 3);
#pragma unroll
                    for (int e = 0; e < 4; e++) {
                        int r = rb + ((e >= 2) ? 8 : 0);
                        int n = n0 + cb + (e & 1);
                        if (n < NKEYS) {
                            float v = __expf(5.0f * acc[mi][ni][e]);
                            atomicAdd(&csh[r * CP + __ldg(&g_lab[n])], v);
                        }
                    }
                }
            }
        }
    }

    __syncthreads();
    float* dst = g_part + ((size_t)ng * BDIM + bt * BM) * C;
    for (int i = tid; i < BM * C; i += NTHREADS) {
        int r = i / C, c = i % C;
        dst[i] = csh[r * CP + c];
    }
}

// ---------------- z branch + combine partials ----------------
__global__ void __launch_bounds__(256) zcombine(float* __restrict__ out) {
    __shared__ float a2[64][17];
    __shared__ float b2[64][17];
    int tid = threadIdx.x;
    int tx = tid & 15, ty = tid >> 4;
    int rb = blockIdx.x * 64, cb = blockIdx.y * 64;

    float acc[4][4];
#pragma unroll
    for (int i = 0; i < 4; i++)
#pragma unroll
        for (int j = 0; j < 4; j++) acc[i][j] = 0.f;

    for (int k0 = 0; k0 < D; k0 += 16) {
        __syncthreads();
#pragma unroll
        for (int j = 0; j < 4; j++) {
            int idx = tid + j * 256;
            int r = idx >> 4, c = idx & 15;
            a2[r][c] = g_qf[(rb + r) * D + k0 + c];
            int cls = cb + r;
            b2[r][c] = (cls < C) ? g_tf[cls * D + k0 + c] : 0.f;
        }
        __syncthreads();
#pragma unroll
        for (int k = 0; k < 16; k++) {
            float av[4], bv[4];
#pragma unroll
            for (int i = 0; i < 4; i++) { av[i] = a2[ty * 4 + i][k]; bv[i] = b2[tx * 4 + i][k]; }
#pragma unroll
            for (int i = 0; i < 4; i++)
#pragma unroll
                for (int j = 0; j < 4; j++) acc[i][j] += av[i] * bv[j];
        }
    }

#pragma unroll
    for (int i = 0; i < 4; i++)
#pragma unroll
        for (int j = 0; j < 4; j++) {
            int r = rb + ty * 4 + i, c = cb + tx * 4 + j;
            if (c < C) {
                float s = 0.f;
#pragma unroll
                for (int gg = 0; gg < NGROUPS; gg++)
                    s += g_part[((size_t)gg * BDIM + r) * C + c];
                out[r * C + c] = 50.f * acc[i][j] + 0.5f * s;
            }
        }
}

__global__ void prep_t(const float* __restrict__ txt) {
    int row = blockIdx.x, t = threadIdx.x;
    float4 x = ((const float4*)(txt + row * D))[t];
    float ss = x.x * x.x + x.y * x.y + x.z * x.z + x.w * x.w;
#pragma unroll
    for (int o = 16; o; o >>= 1) ss += __shfl_xor_sync(FULLM, ss, o);
    __shared__ float ws[4];
    if ((t & 31) == 0) ws[t >> 5] = ss;
    __syncthreads();
    float inv = rsqrtf(ws[0] + ws[1] + ws[2] + ws[3]);
    ((float4*)(g_tf + row * D))[t] = make_float4(x.x * inv, x.y * inv, x.z * inv, x.w * inv);
}

// ---------------- launch ----------------
extern "C" void kernel_launch(void* const* d_in, const int* in_sizes, int n_in,
                              void* d_out, int out_size) {
    const float* img  = (const float*)d_in[0];
    const float* txt  = (const float*)d_in[1];
    const float* keys = (const float*)d_in[2];
    const int*   labs = (const int*)d_in[3];
    float* out = (float*)d_out;

    cudaFuncSetAttribute(gemm_scatter, cudaFuncAttributeMaxDynamicSharedMemorySize,
                         SMEM_DYN);

    prep_zero<<<1, 256>>>();
    prep_hist<<<(NKEYS + 255) / 256, 256>>>(labs);
    prep_scan<<<1, 256>>>();
    prep_perm<<<(NKEYS + 255) / 256, 256>>>(labs);
    prep_q<<<BDIM / 16, 512>>>(img);
    prep_t<<<C, 128>>>(txt);
    prep_k<<<NKEYS / 16, 512>>>(keys);
    gemm_scatter<<<dim3(BTILES, NGROUPS), NTHREADS, SMEM_DYN>>>();
    zcombine<<<dim3(BDIM / 64, 4), 256>>>(out);
}

// round 17
// speedup vs baseline: 1.1706x; 1.0463x over previous
#include <cuda_runtime.h>
#include <cuda_bf16.h>
#include <cstdint>
#include <cstring>

typedef unsigned int u32;
#define FULLM 0xffffffffu

#define D        512
#define KT       32
#define BDIM     1024
#define C        200
#define NKEYS    50000
#define BM       128
#define BN       128
#define NTILES   391
#define NPAD     (NTILES * BN)       // 50048
#define NT16     (NPAD / 16)         // 3128
#define BTILES   (BDIM / BM)         // 8
#define NGROUPS  18                  // 144 CTAs = one wave
#define NTHREADS 512
#define CP       201
#define SMEM_DYN (BM * CP * 4)       // 102912

// ---------------- device scratch ----------------
__device__ __align__(16) uint4 g_qfrag[BDIM / 16][KT][32];
__device__ __align__(16) uint4 g_kfrag[NT16][KT][32];    // tail tiles stay zero
__device__ float g_qf[BDIM * D];
__device__ float g_tf[C * D];
__device__ int   g_lab[NPAD];        // label-sorted; tail stays 0
__device__ int   g_perm[NPAD];       // sorted pos -> source row
__device__ int   g_hist[C];
__device__ int   g_cur[C];
__device__ float g_part[NGROUPS * BDIM * C];

// ---------------- helpers ----------------
__device__ __forceinline__ u32 bf2u(__nv_bfloat162 v) {
    u32 r;
    memcpy(&r, &v, 4);
    return r;
}

__device__ __forceinline__ void mma_bf16(float* d, const u32* a, const u32* b) {
    asm("mma.sync.aligned.m16n8k16.row.col.f32.bf16.bf16.f32 "
        "{%0,%1,%2,%3}, {%4,%5,%6,%7}, {%8,%9}, {%0,%1,%2,%3};\n"
        : "+f"(d[0]), "+f"(d[1]), "+f"(d[2]), "+f"(d[3])
        : "r"(a[0]), "r"(a[1]), "r"(a[2]), "r"(a[3]), "r"(b[0]), "r"(b[1]));
}

__device__ __forceinline__ uint4 ldg_keep(const uint4* p) {
    uint4 v;
    asm("ld.global.nc.L1::evict_last.v4.u32 {%0,%1,%2,%3}, [%4];"
        : "=r"(v.x), "=r"(v.y), "=r"(v.z), "=r"(v.w) : "l"(p));
    return v;
}
__device__ __forceinline__ uint4 ldg_stream(const uint4* p) {
    uint4 v;
    asm("ld.global.nc.L1::evict_first.v4.u32 {%0,%1,%2,%3}, [%4];"
        : "=r"(v.x), "=r"(v.y), "=r"(v.z), "=r"(v.w) : "l"(p));
    return v;
}

// ---------------- sort prep ----------------
__global__ void prep_hist(const int* __restrict__ labels) {
    int i = blockIdx.x * blockDim.x + threadIdx.x;
    if (i < NKEYS) {
        int l = labels[i];
        l = (l < 0) ? 0 : ((l >= C) ? C - 1 : l);
        atomicAdd(&g_hist[l], 1);
    }
}
__global__ void prep_scan() {
    __shared__ int sh[C];
    int t = threadIdx.x;
    if (t < C) sh[t] = g_hist[t];
    __syncthreads();
    if (t == 0) {
        int acc = 0;
        for (int c = 0; c < C; c++) { int v = sh[c]; sh[c] = acc; acc += v; }
    }
    __syncthreads();
    if (t < C) g_cur[t] = sh[t];
}
// block-aggregated scatter: smem hist + one global atomic per (block, class)
__global__ void prep_perm(const int* __restrict__ labels) {
    __shared__ int scnt[C];
    __shared__ int sbase[C];
    int t = threadIdx.x;
    if (t < C) scnt[t] = 0;
    __syncthreads();
    int i = blockIdx.x * blockDim.x + t;
    int l = 0, rk = 0;
    bool valid = (i < NKEYS);
    if (valid) {
        l = labels[i];
        l = (l < 0) ? 0 : ((l >= C) ? C - 1 : l);
        rk = atomicAdd(&scnt[l], 1);
    }
    __syncthreads();
    if (t < C && scnt[t] > 0) sbase[t] = atomicAdd(&g_cur[t], scnt[t]);
    __syncthreads();
    if (valid) {
        int p = sbase[l] + rk;
        g_perm[p] = i;
        g_lab[p] = l;
    }
}

// ---------------- prep: normalize + fragment-major tiles ----------------
__global__ void __launch_bounds__(512) prep_q(const float* __restrict__ img) {
    __shared__ u32 sh[16][260];
    int t = threadIdx.x, w = t >> 5, l = t & 31;
    if (blockIdx.x == 0 && t < C) g_hist[t] = 0;    // folded prep_zero
    int row = blockIdx.x * 16 + w;
    const float4* src = (const float4*)(img + row * D);
    float4 v[4]; float ss = 0.f;
#pragma unroll
    for (int j = 0; j < 4; j++) {
        v[j] = src[j * 32 + l];
        ss += v[j].x * v[j].x + v[j].y * v[j].y + v[j].z * v[j].z + v[j].w * v[j].w;
    }
#pragma unroll
    for (int o = 16; o; o >>= 1) ss += __shfl_xor_sync(FULLM, ss, o);
    float inv = rsqrtf(ss);
    float4* qf = (float4*)(g_qf + row * D);
#pragma unroll
    for (int j = 0; j < 4; j++) {
        float4 y = make_float4(v[j].x * inv, v[j].y * inv, v[j].z * inv, v[j].w * inv);
        qf[j * 32 + l] = y;
        int col = (j * 32 + l) * 2;
        sh[w][col]     = bf2u(__floats2bfloat162_rn(y.x, y.y));
        sh[w][col + 1] = bf2u(__floats2bfloat162_rn(y.z, y.w));
    }
    __syncthreads();
#pragma unroll
    for (int s = t; s < 1024; s += 512) {
        int kt = s >> 5, ln = s & 31;
        int ka = kt * 8 + (ln & 3), kb = ka + 4, r0 = ln >> 2;
        uint4 f;
        f.x = sh[r0][ka]; f.y = sh[r0 + 8][ka]; f.z = sh[r0][kb]; f.w = sh[r0 + 8][kb];
        g_qfrag[blockIdx.x][kt][ln] = f;
    }
}

// gather sorted rows via perm; fragment build unchanged
__global__ void __launch_bounds__(512) prep_k(const float* __restrict__ keys) {
    __shared__ u32 sh[16][260];
    int t = threadIdx.x, w = t >> 5, l = t & 31;
    int srcrow = __ldg(&g_perm[blockIdx.x * 16 + w]);
    const float4* src = (const float4*)(keys + (size_t)srcrow * D);
    float4 v[4]; float ss = 0.f;
#pragma unroll
    for (int j = 0; j < 4; j++) {
        v[j] = src[j * 32 + l];
        ss += v[j].x * v[j].x + v[j].y * v[j].y + v[j].z * v[j].z + v[j].w * v[j].w;
    }
#pragma unroll
    for (int o = 16; o; o >>= 1) ss += __shfl_xor_sync(FULLM, ss, o);
    float inv = rsqrtf(ss);
#pragma unroll
    for (int j = 0; j < 4; j++) {
        int col = (j * 32 + l) * 2;
        sh[w][col]     = bf2u(__floats2bfloat162_rn(v[j].x * inv, v[j].y * inv));
        sh[w][col + 1] = bf2u(__floats2bfloat162_rn(v[j].z * inv, v[j].w * inv));
    }
    __syncthreads();
#pragma unroll
    for (int s = t; s < 1024; s += 512) {
        int kt = s >> 5, ln = s & 31;
        int ka = kt * 8 + (ln & 3), kb = ka + 4, n0 = ln >> 2;
        uint4 f;
        f.x = sh[n0][ka]; f.y = sh[n0][kb]; f.z = sh[n0 + 8][ka]; f.w = sh[n0 + 8][kb];
        g_kfrag[blockIdx.x][kt][ln] = f;
    }
}

// ---------------- main: fragment GEMM + sorted-label quad-merged scatter ----------------
extern __shared__ float csh[];

__global__ void __launch_bounds__(NTHREADS, 1) gemm_scatter() {
    int tid = threadIdx.x;
    int lane = tid & 31, wid = tid >> 5;
    int wm = wid >> 2, wn = wid & 3;          // 4x4 warps, warp tile 32x32
    int bt = blockIdx.x;
    int ng = blockIdx.y;

    for (int i = tid; i < BM * CP; i += NTHREADS) csh[i] = 0.f;
    __syncthreads();

    int mt0 = bt * 8 + wm * 2;
    const uint4* A0 = &g_qfrag[mt0][0][lane];
    const uint4* A1 = &g_qfrag[mt0 + 1][0][lane];

    const int coff[8] = {0, 1, 8, 9, 16, 17, 24, 25};   // ascending thread cols

    int nt = (NTILES - 1 - ng) / NGROUPS + 1;
    for (int tl = 0; tl < nt; tl++) {
        int ntile = ng + tl * NGROUPS;
        int n0 = ntile * BN;
        const uint4* B0 = &g_kfrag[ntile * 8 + wn * 2][0][lane];
        const uint4* B1 = B0 + KT * 32;

        float acc[2][4][4];
#pragma unroll
        for (int mi = 0; mi < 2; mi++)
#pragma unroll
            for (int ni = 0; ni < 4; ni++)
#pragma unroll
                for (int e = 0; e < 4; e++) acc[mi][ni][e] = 0.f;

#pragma unroll 8
        for (int kt = 0; kt < KT; kt++) {
            uint4 av0 = ldg_keep(A0 + kt * 32);
            uint4 av1 = ldg_keep(A1 + kt * 32);
            uint4 bv0 = ldg_stream(B0 + kt * 32);
            uint4 bv1 = ldg_stream(B1 + kt * 32);
            u32 Ar0[4] = {av0.x, av0.y, av0.z, av0.w};
            u32 Ar1[4] = {av1.x, av1.y, av1.z, av1.w};
            u32 Bp[4][2] = {{bv0.x, bv0.y}, {bv0.z, bv0.w},
                            {bv1.x, bv1.y}, {bv1.z, bv1.w}};
#pragma unroll
            for (int ni = 0; ni < 4; ni++) {
                mma_bf16(acc[0][ni], Ar0, Bp[ni]);
                mma_bf16(acc[1][ni], Ar1, Bp[ni]);
            }
        }

        if (n0 + BN <= NKEYS) {                   // full tile: sorted-label fast path
            int c0 = n0 + wn * 32 + 2 * (lane & 3);
            int l0  = __ldg(&g_lab[c0]);
            int l25 = __ldg(&g_lab[c0 + 25]);
            int pure = (l0 == l25) ? 1 : 0;
            int p = pure, lq = l0;
            int p1 = __shfl_xor_sync(FULLM, p, 1);
            int l1 = __shfl_xor_sync(FULLM, lq, 1);
            p = p & p1 & (lq == l1);
            int p2 = __shfl_xor_sync(FULLM, p, 2);
            int l2 = __shfl_xor_sync(FULLM, lq, 2);
            p = p & p2 & (lq == l2);

#pragma unroll
            for (int mi = 0; mi < 2; mi++) {
                int rA = wm * 32 + mi * 16 + (lane >> 2);
                float v0[8], v1[8];
#pragma unroll
                for (int ni = 0; ni < 4; ni++) {
                    v0[ni * 2]     = __expf(5.0f * acc[mi][ni][0]);
                    v0[ni * 2 + 1] = __expf(5.0f * acc[mi][ni][1]);
                    v1[ni * 2]     = __expf(5.0f * acc[mi][ni][2]);
                    v1[ni * 2 + 1] = __expf(5.0f * acc[mi][ni][3]);
                }
                float s0 = 0.f, s1 = 0.f;
#pragma unroll
                for (int k = 0; k < 8; k++) { s0 += v0[k]; s1 += v1[k]; }
                float t0 = s0 + __shfl_xor_sync(FULLM, s0, 1);
                t0 += __shfl_xor_sync(FULLM, t0, 2);
                float t1 = s1 + __shfl_xor_sync(FULLM, s1, 1);
                t1 += __shfl_xor_sync(FULLM, t1, 2);
                if (p) {
                    if ((lane & 3) == 0) {
                        atomicAdd(&csh[rA * CP + lq], t0);
                        atomicAdd(&csh[(rA + 8) * CP + lq], t1);
                    }
                } else if (pure) {
                    atomicAdd(&csh[rA * CP + l0], s0);
                    atomicAdd(&csh[(rA + 8) * CP + l0], s1);
                } else {
                    int cur = -1; float r0 = 0.f, r1 = 0.f;
#pragma unroll
                    for (int k = 0; k < 8; k++) {
                        int lk = __ldg(&g_lab[c0 + coff[k]]);
                        if (lk != cur) {
                            if (cur >= 0) {
                                atomicAdd(&csh[rA * CP + cur], r0);
                                atomicAdd(&csh[(rA + 8) * CP + cur], r1);
                            }
                            cur = lk; r0 = 0.f; r1 = 0.f;
                        }
                        r0 += v0[k]; r1 += v1[k];
                    }
                    atomicAdd(&csh[rA * CP + cur], r0);
                    atomicAdd(&csh[(rA + 8) * CP + cur], r1);
                }
            }
        } else {                                  // tail tile (ntile==390): guarded path
#pragma unroll
            for (int mi = 0; mi < 2; mi++) {
#pragma unroll
                for (int ni = 0; ni < 4; ni++) {
                    int rb = wm * 32 + mi * 16 + (lane >> 2);
                    int cb = wn * 32 + ni * 8 + 2 * (lane & 3);
#pragma unroll
                    for (int e = 0; e < 4; e++) {
                        int r = rb + ((e >= 2) ? 8 : 0);
                        int n = n0 + cb + (e & 1);
                        if (n < NKEYS) {
                            float v = __expf(5.0f * acc[mi][ni][e]);
                            atomicAdd(&csh[r * CP + __ldg(&g_lab[n])], v);
                        }
                    }
                }
            }
        }
    }

    __syncthreads();
    float* dst = g_part + ((size_t)ng * BDIM + bt * BM) * C;
    for (int i = tid; i < BM * C; i += NTHREADS) {
        int r = i / C, c = i % C;
        dst[i] = csh[r * CP + c];
    }
}

// ---------------- z branch + combine partials ----------------
__global__ void __launch_bounds__(256) zcombine(float* __restrict__ out) {
    __shared__ float a2[64][17];
    __shared__ float b2[64][17];
    int tid = threadIdx.x;
    int tx = tid & 15, ty = tid >> 4;
    int rb = blockIdx.x * 64, cb = blockIdx.y * 64;

    float acc[4][4];
#pragma unroll
    for (int i = 0; i < 4; i++)
#pragma unroll
        for (int j = 0; j < 4; j++) acc[i][j] = 0.f;

    for (int k0 = 0; k0 < D; k0 += 16) {
        __syncthreads();
#pragma unroll
        for (int j = 0; j < 4; j++) {
            int idx = tid + j * 256;
            int r = idx >> 4, c = idx & 15;
            a2[r][c] = g_qf[(rb + r) * D + k0 + c];
            int cls = cb + r;
            b2[r][c] = (cls < C) ? g_tf[cls * D + k0 + c] : 0.f;
        }
        __syncthreads();
#pragma unroll
        for (int k = 0; k < 16; k++) {
            float av[4], bv[4];
#pragma unroll
            for (int i = 0; i < 4; i++) { av[i] = a2[ty * 4 + i][k]; bv[i] = b2[tx * 4 + i][k]; }
#pragma unroll
            for (int i = 0; i < 4; i++)
#pragma unroll
                for (int j = 0; j < 4; j++) acc[i][j] += av[i] * bv[j];
        }
    }

#pragma unroll
    for (int i = 0; i < 4; i++)
#pragma unroll
        for (int j = 0; j < 4; j++) {
            int r = rb + ty * 4 + i, c = cb + tx * 4 + j;
            if (c < C) {
                float s = 0.f;
#pragma unroll
                for (int gg = 0; gg < NGROUPS; gg++)
                    s += g_part[((size_t)gg * BDIM + r) * C + c];
                out[r * C + c] = 50.f * acc[i][j] + 0.5f * s;
            }
        }
}

__global__ void prep_t(const float* __restrict__ txt) {
    int row = blockIdx.x, t = threadIdx.x;
    float4 x = ((const float4*)(txt + row * D))[t];
    float ss = x.x * x.x + x.y * x.y + x.z * x.z + x.w * x.w;
#pragma unroll
    for (int o = 16; o; o >>= 1) ss += __shfl_xor_sync(FULLM, ss, o);
    __shared__ float ws[4];
    if ((t & 31) == 0) ws[t >> 5] = ss;
    __syncthreads();
    float inv = rsqrtf(ws[0] + ws[1] + ws[2] + ws[3]);
    ((float4*)(g_tf + row * D))[t] = make_float4(x.x * inv, x.y * inv, x.z * inv, x.w * inv);
}

// ---------------- launch ----------------
extern "C" void kernel_launch(void* const* d_in, const int* in_sizes, int n_in,
                              void* d_out, int out_size) {
    const float* img  = (const float*)d_in[0];
    const float* txt  = (const float*)d_in[1];
    const float* keys = (const float*)d_in[2];
    const int*   labs = (const int*)d_in[3];
    float* out = (float*)d_out;

    cudaFuncSetAttribute(gemm_scatter, cudaFuncAttributeMaxDynamicSharedMemorySize,
                         SMEM_DYN);

    prep_q<<<BDIM / 16, 512>>>(img);     // also zeroes g_hist (block 0)
    prep_hist<<<(NKEYS + 255) / 256, 256>>>(labs);
    prep_scan<<<1, 256>>>();
    prep_perm<<<(NKEYS + 255) / 256, 256>>>(labs);
    prep_t<<<C, 128>>>(txt);
    prep_k<<<NKEYS / 16, 512>>>(keys);
    gemm_scatter<<<dim3(BTILES, NGROUPS), NTHREADS, SMEM_DYN>>>();
    zcombine<<<dim3(BDIM / 64, 4), 256>>>(out);
}